// round 2
// baseline (speedup 1.0000x reference)
#include <cuda_runtime.h>
#include <math.h>

// ---------------- problem constants ----------------
#define B_ 16
#define T_ 2048
#define H_ 1024
#define H4 (H_ / 4)      // 256 float4 per row
#define BT 128           // timesteps per block in alphas kernel

// ---------------- device scratch (no allocations allowed) ----------------
__device__ float g_alphas[B_ * T_];
__device__ float g_dist[B_ * T_];
__device__ float g_rem[B_ * T_];
__device__ int   g_fire_t[B_ * T_];
__device__ int   g_nf[B_];
__device__ float g_dummy_len[B_];
__device__ float g_dummy_fires[B_ * T_];

// ---------------- kernel A: alphas = sigmoid(lin(relu(dwconv3(x)+x))) ------
// grid (T/BT, B), block 256 threads; each thread owns 4 h's (one float4 lane
// group). 3-tap stencil kept in registers (hidden read exactly once).
__device__ __forceinline__ float part1(float xm, float x0, float xp,
                                       float w0, float w1, float w2,
                                       float cb, float lw) {
    float v = fmaf(w0, xm, fmaf(w1, x0, fmaf(w2, xp, cb)));
    v += x0;                 // residual
    v = fmaxf(v, 0.0f);      // relu
    return lw * v;
}

__global__ __launch_bounds__(256) void alphas_kernel(
    const float* __restrict__ hidden, const float* __restrict__ conv_w,
    const float* __restrict__ conv_b, const float* __restrict__ lin_w,
    const float* __restrict__ lin_b)
{
    const int b = blockIdx.y;
    const int tstart = blockIdx.x * BT;
    const int tid = threadIdx.x;
    const int lane = tid & 31;
    const int warp = tid >> 5;

    __shared__ float wpart[4][8];   // [t within group][warp]

    const int h0 = tid * 4;
    float w0[4], w1[4], w2[4], cb[4], lw[4];
#pragma unroll
    for (int j = 0; j < 4; j++) {
        w0[j] = conv_w[(h0 + j) * 3 + 0];
        w1[j] = conv_w[(h0 + j) * 3 + 1];
        w2[j] = conv_w[(h0 + j) * 3 + 2];
        cb[j] = conv_b[h0 + j];
        lw[j] = lin_w[h0 + j];
    }
    const float lb = lin_b[0];

    const float4* Hb = (const float4*)hidden + (size_t)b * T_ * H4;
    const float4 z4 = make_float4(0.f, 0.f, 0.f, 0.f);

    float4 xm = (tstart > 0) ? Hb[(size_t)(tstart - 1) * H4 + tid] : z4;
    float4 x0 = Hb[(size_t)tstart * H4 + tid];

    for (int c = 0; c < BT / 4; ++c) {
        const int t0 = tstart + c * 4;
        // prefetch 4 future rows together (MLP=4 per thread)
        float4 xA = Hb[(size_t)(t0 + 1) * H4 + tid];
        float4 xB = Hb[(size_t)(t0 + 2) * H4 + tid];
        float4 xC = Hb[(size_t)(t0 + 3) * H4 + tid];
        float4 xD = (t0 + 4 < T_) ? Hb[(size_t)(t0 + 4) * H4 + tid] : z4;

        float s[4];
        {
            const float4* P[6] = { &xm, &x0, &xA, &xB, &xC, &xD };
#pragma unroll
            for (int i = 0; i < 4; i++) {
                const float4 a = *P[i], m = *P[i + 1], p = *P[i + 2];
                float acc;
                acc  = part1(a.x, m.x, p.x, w0[0], w1[0], w2[0], cb[0], lw[0]);
                acc += part1(a.y, m.y, p.y, w0[1], w1[1], w2[1], cb[1], lw[1]);
                acc += part1(a.z, m.z, p.z, w0[2], w1[2], w2[2], cb[2], lw[2]);
                acc += part1(a.w, m.w, p.w, w0[3], w1[3], w2[3], cb[3], lw[3]);
                s[i] = acc;
            }
        }
        // 4 independent warp reductions (ILP hides shfl latency)
#pragma unroll
        for (int i = 0; i < 4; i++) {
#pragma unroll
            for (int off = 16; off; off >>= 1)
                s[i] += __shfl_xor_sync(0xffffffffu, s[i], off);
        }
        if (lane == 0) {
#pragma unroll
            for (int i = 0; i < 4; i++) wpart[i][warp] = s[i];
        }
        __syncthreads();
        if (tid < 4) {
            float tot = lb;
#pragma unroll
            for (int w = 0; w < 8; w++) tot += wpart[tid][w];
            g_alphas[b * T_ + t0 + tid] = 1.0f / (1.0f + expf(-tot));
        }
        __syncthreads();
        xm = xC;
        x0 = xD;
    }
}

// ---------------- kernel S: exact sequential integrate-and-fire scan -------
// One block per batch. Thread 0 replicates the reference's fp32 sequence
// exactly: i += a; fire = (i >= 1); i -= fire. Subtract of 1.0 on [1,2) is
// exact (Sterbenz), so fire pattern matches the reference's scan.
__global__ void scan_kernel(float* __restrict__ out_fires,
                            float* __restrict__ out_len)
{
    const int b = blockIdx.x;
    __shared__ float a_s[T_];
    const float* ab = g_alphas + b * T_;
    for (int i = threadIdx.x; i < T_; i += blockDim.x) a_s[i] = ab[i];
    __syncthreads();

    if (threadIdx.x == 0) {
        float integ = 0.0f;
        int nf = 0;
        float* fires = out_fires + b * T_;
        const int base = b * T_;
        for (int t = 0; t < T_; ++t) {
            const float a = a_s[t];
            const float before = integ;
            integ += a;
            fires[t] = integ;                     // fires recorded pre-subtract
            const bool fire = (integ >= 1.0f);
            if (fire) {
                const float dist = 1.0f - before; // distribution completion
                g_dist[base + t]   = dist;
                g_rem[base + t]    = a - dist;    // remainder opens next segment
                g_fire_t[base + nf] = t;
            }
            nf    += fire ? 1 : 0;
            integ -= fire ? 1.0f : 0.0f;          // FSEL path, short chain
        }
        g_nf[b] = nf;
        out_len[b] = integ + (float)nf;           // == fp-sum of alphas (~1e-7 rel)
    }
}

// ---------------- kernel C: per-output-row segment gather ------------------
// grid (L, B), block 256 threads x float4 = 1024 h. Row r of batch b:
//   acc = rem[t_{r-1}]*h[t_{r-1}] + sum_{t in (t_{r-1}, t_r)} alpha_t*h[t]
//         + dist[t_r]*h[t_r]
// accumulated in the reference's (time-ascending) order. Padding rows -> 0.
__global__ __launch_bounds__(256) void gather_kernel(
    const float* __restrict__ hidden, float* __restrict__ out, int L)
{
    const int b = blockIdx.y;
    const int r = blockIdx.x;
    const int tid = threadIdx.x;

    float4* orow = (float4*)out + ((size_t)b * L + r) * H4;
    const int nf = g_nf[b];
    if (r >= nf) {
        orow[tid] = make_float4(0.f, 0.f, 0.f, 0.f);
        return;
    }
    const int base = b * T_;
    const int t1 = g_fire_t[base + r];
    const float4* Hb = (const float4*)hidden + (size_t)b * T_ * H4;

    float4 acc = make_float4(0.f, 0.f, 0.f, 0.f);
    int ts = 0;
    if (r > 0) {
        const int t0 = g_fire_t[base + r - 1];
        const float rem = g_rem[base + t0];
        const float4 h = Hb[(size_t)t0 * H4 + tid];
        acc.x = rem * h.x; acc.y = rem * h.y;
        acc.z = rem * h.z; acc.w = rem * h.w;
        ts = t0 + 1;
    }
    for (int t = ts; t < t1; ++t) {
        const float a = g_alphas[base + t];        // uniform -> L1 broadcast
        const float4 h = Hb[(size_t)t * H4 + tid];
        acc.x = fmaf(a, h.x, acc.x); acc.y = fmaf(a, h.y, acc.y);
        acc.z = fmaf(a, h.z, acc.z); acc.w = fmaf(a, h.w, acc.w);
    }
    {
        const float dist = g_dist[base + t1];
        const float4 h = Hb[(size_t)t1 * H4 + tid];
        acc.x = fmaf(dist, h.x, acc.x); acc.y = fmaf(dist, h.y, acc.y);
        acc.z = fmaf(dist, h.z, acc.z); acc.w = fmaf(dist, h.w, acc.w);
    }
    orow[tid] = acc;
}

// ---------------- launch ---------------------------------------------------
extern "C" void kernel_launch(void* const* d_in, const int* in_sizes, int n_in,
                              void* d_out, int out_size)
{
    const float* hidden = (const float*)d_in[0];
    const float* conv_w = (const float*)d_in[1];
    const float* conv_b = (const float*)d_in[2];
    const float* lin_w  = (const float*)d_in[3];
    const float* lin_b  = (const float*)d_in[4];

    float* out = (float*)d_out;

    // Output layout: tuple (cif_output[B,L,H], cif_length[B], fires[B,T])
    // flattened in order. L is fixed by out_size. The two layout hypotheses
    // are mutually exclusive mod B*H (32784 % 16384 = 16 != 0).
    const long long fixed = (long long)B_ + (long long)B_ * T_;
    long long rem = (long long)out_size - fixed;
    int L;
    float* out_cif;
    float* out_len;
    float* out_fires;
    if (rem > 0 && rem % ((long long)B_ * H_) == 0) {
        L = (int)(rem / ((long long)B_ * H_));
        out_cif   = out;
        out_len   = out + (size_t)B_ * L * H_;
        out_fires = out_len + B_;
    } else {
        // fallback: single-output mode (cif_output only)
        L = (int)((long long)out_size / ((long long)B_ * H_));
        out_cif = out;
        cudaGetSymbolAddress((void**)&out_len, g_dummy_len);
        cudaGetSymbolAddress((void**)&out_fires, g_dummy_fires);
    }

    alphas_kernel<<<dim3(T_ / BT, B_), 256>>>(hidden, conv_w, conv_b,
                                              lin_w, lin_b);
    scan_kernel<<<B_, 64>>>(out_fires, out_len);
    if (L > 0)
        gather_kernel<<<dim3(L, B_), 256>>>(hidden, out_cif, L);
}

// round 3
// speedup vs baseline: 1.3816x; 1.3816x over previous
#include <cuda_runtime.h>
#include <math.h>

// ---------------- problem constants ----------------
#define B_ 16
#define T_ 2048
#define H_ 1024
#define H4 (H_ / 4)      // 256 float4 per row
#define BT 32            // timesteps per block in alphas kernel (grid = 1024)

// ---------------- device scratch (no allocations allowed) ----------------
__device__ float g_alphas[B_ * T_];
__device__ float g_dist[B_ * T_];
__device__ float g_rem[B_ * T_];
__device__ int   g_fire_t[B_ * T_];
__device__ int   g_nf[B_];
__device__ float g_dummy_len[B_];
__device__ float g_dummy_fires[B_ * T_];

// ---------------- kernel A: alphas = sigmoid(lin(relu(dwconv3(x)+x))) ------
__device__ __forceinline__ float part1(float xm, float x0, float xp,
                                       float w0, float w1, float w2,
                                       float cb, float lw) {
    float v = fmaf(w0, xm, fmaf(w1, x0, fmaf(w2, xp, cb)));
    v += x0;                 // residual
    v = fmaxf(v, 0.0f);      // relu
    return lw * v;
}

__global__ __launch_bounds__(256) void alphas_kernel(
    const float* __restrict__ hidden, const float* __restrict__ conv_w,
    const float* __restrict__ conv_b, const float* __restrict__ lin_w,
    const float* __restrict__ lin_b)
{
    const int b = blockIdx.y;
    const int tstart = blockIdx.x * BT;
    const int tid = threadIdx.x;
    const int lane = tid & 31;
    const int warp = tid >> 5;

    __shared__ float wpart[4][8];   // [t within group][warp]

    const int h0 = tid * 4;
    float w0[4], w1[4], w2[4], cb[4], lw[4];
#pragma unroll
    for (int j = 0; j < 4; j++) {
        w0[j] = conv_w[(h0 + j) * 3 + 0];
        w1[j] = conv_w[(h0 + j) * 3 + 1];
        w2[j] = conv_w[(h0 + j) * 3 + 2];
        cb[j] = conv_b[h0 + j];
        lw[j] = lin_w[h0 + j];
    }
    const float lb = lin_b[0];

    const float4* Hb = (const float4*)hidden + (size_t)b * T_ * H4;
    const float4 z4 = make_float4(0.f, 0.f, 0.f, 0.f);

    float4 xm = (tstart > 0) ? Hb[(size_t)(tstart - 1) * H4 + tid] : z4;
    float4 x0 = Hb[(size_t)tstart * H4 + tid];

    for (int c = 0; c < BT / 4; ++c) {
        const int t0 = tstart + c * 4;
        // prefetch 4 future rows together (MLP=4 per thread)
        float4 xA = Hb[(size_t)(t0 + 1) * H4 + tid];
        float4 xB = Hb[(size_t)(t0 + 2) * H4 + tid];
        float4 xC = Hb[(size_t)(t0 + 3) * H4 + tid];
        float4 xD = (t0 + 4 < T_) ? Hb[(size_t)(t0 + 4) * H4 + tid] : z4;

        float s[4];
        {
            const float4* P[6] = { &xm, &x0, &xA, &xB, &xC, &xD };
#pragma unroll
            for (int i = 0; i < 4; i++) {
                const float4 a = *P[i], m = *P[i + 1], p = *P[i + 2];
                float acc;
                acc  = part1(a.x, m.x, p.x, w0[0], w1[0], w2[0], cb[0], lw[0]);
                acc += part1(a.y, m.y, p.y, w0[1], w1[1], w2[1], cb[1], lw[1]);
                acc += part1(a.z, m.z, p.z, w0[2], w1[2], w2[2], cb[2], lw[2]);
                acc += part1(a.w, m.w, p.w, w0[3], w1[3], w2[3], cb[3], lw[3]);
                s[i] = acc;
            }
        }
        // 4 independent warp reductions (ILP hides shfl latency)
#pragma unroll
        for (int i = 0; i < 4; i++) {
#pragma unroll
            for (int off = 16; off; off >>= 1)
                s[i] += __shfl_xor_sync(0xffffffffu, s[i], off);
        }
        if (lane == 0) {
#pragma unroll
            for (int i = 0; i < 4; i++) wpart[i][warp] = s[i];
        }
        __syncthreads();
        if (tid < 4) {
            float tot = lb;
#pragma unroll
            for (int w = 0; w < 8; w++) tot += wpart[tid][w];
            g_alphas[b * T_ + t0 + tid] = 1.0f / (1.0f + expf(-tot));
        }
        __syncthreads();
        xm = xC;
        x0 = xD;
    }
}

// ---------------- kernel S: exact sequential integrate-and-fire scan -------
// One block per batch; thread 0 runs a fully BRANCHLESS 2048-step chain:
//   t1 = integ + a        (FADD, 4)
//   p  = t1 >= 1          (FSETP -> data, 4)
//   integ' = p ? t1-1 : t1 (FSEL, 4)   -> 12-cycle dependent chain
// dist/rem/fire_t are stored UNCONDITIONALLY (only fire positions are ever
// read; non-fire fire_t slots are overwritten since nf doesn't advance).
// Outputs staged in smem (STS is issue-only) and flushed by all threads.
__global__ __launch_bounds__(64) void scan_kernel(float* __restrict__ out_fires,
                                                  float* __restrict__ out_len)
{
    const int b = blockIdx.x;
    __shared__ float a_s[T_];
    __shared__ float fires_s[T_];
    __shared__ float dist_s[T_];
    __shared__ float rem_s[T_];

    const float* ab = g_alphas + b * T_;
    for (int i = threadIdx.x; i < T_; i += blockDim.x) a_s[i] = ab[i];
    __syncthreads();

    if (threadIdx.x == 0) {
        float integ = 0.0f;
        int nf = 0;
        const int base = b * T_;
        for (int t = 0; t < T_; t += 8) {
            float av[8];
#pragma unroll
            for (int j = 0; j < 8; j++) av[j] = a_s[t + j];
#pragma unroll
            for (int j = 0; j < 8; j++) {
                const float a = av[j];
                const float t1 = integ + a;        // fires value (pre-subtract)
                const float dist = 1.0f - integ;   // distribution completion
                const float t2 = t1 - 1.0f;        // exact on [1,2) (Sterbenz)
                const bool fire = (t1 >= 1.0f);
                fires_s[t + j] = t1;
                dist_s[t + j]  = dist;
                rem_s[t + j]   = a - dist;
                g_fire_t[base + nf] = t + j;       // unconditional; kept iff fire
                nf += fire ? 1 : 0;
                integ = fire ? t2 : t1;
            }
        }
        g_nf[b] = nf;
        out_len[b] = integ + (float)nf;            // == fp-sum of alphas
    }
    __syncthreads();

    float* fires = out_fires + b * T_;
    const int base = b * T_;
    for (int i = threadIdx.x; i < T_; i += blockDim.x) {
        fires[i]        = fires_s[i];
        g_dist[base + i] = dist_s[i];
        g_rem[base + i]  = rem_s[i];
    }
}

// ---------------- kernel C: per-output-row segment gather ------------------
__global__ __launch_bounds__(256) void gather_kernel(
    const float* __restrict__ hidden, float* __restrict__ out, int L)
{
    const int b = blockIdx.y;
    const int r = blockIdx.x;
    const int tid = threadIdx.x;

    float4* orow = (float4*)out + ((size_t)b * L + r) * H4;
    const int nf = g_nf[b];
    if (r >= nf) {
        orow[tid] = make_float4(0.f, 0.f, 0.f, 0.f);
        return;
    }
    const int base = b * T_;
    const int t1 = g_fire_t[base + r];
    const float4* Hb = (const float4*)hidden + (size_t)b * T_ * H4;

    float4 acc = make_float4(0.f, 0.f, 0.f, 0.f);
    int ts = 0;
    if (r > 0) {
        const int t0 = g_fire_t[base + r - 1];
        const float rem = g_rem[base + t0];
        const float4 h = Hb[(size_t)t0 * H4 + tid];
        acc.x = rem * h.x; acc.y = rem * h.y;
        acc.z = rem * h.z; acc.w = rem * h.w;
        ts = t0 + 1;
    }
    for (int t = ts; t < t1; ++t) {
        const float a = g_alphas[base + t];        // uniform -> broadcast
        const float4 h = Hb[(size_t)t * H4 + tid];
        acc.x = fmaf(a, h.x, acc.x); acc.y = fmaf(a, h.y, acc.y);
        acc.z = fmaf(a, h.z, acc.z); acc.w = fmaf(a, h.w, acc.w);
    }
    {
        const float dist = g_dist[base + t1];
        const float4 h = Hb[(size_t)t1 * H4 + tid];
        acc.x = fmaf(dist, h.x, acc.x); acc.y = fmaf(dist, h.y, acc.y);
        acc.z = fmaf(dist, h.z, acc.z); acc.w = fmaf(dist, h.w, acc.w);
    }
    orow[tid] = acc;
}

// ---------------- launch ---------------------------------------------------
extern "C" void kernel_launch(void* const* d_in, const int* in_sizes, int n_in,
                              void* d_out, int out_size)
{
    const float* hidden = (const float*)d_in[0];
    const float* conv_w = (const float*)d_in[1];
    const float* conv_b = (const float*)d_in[2];
    const float* lin_w  = (const float*)d_in[3];
    const float* lin_b  = (const float*)d_in[4];

    float* out = (float*)d_out;

    // Output layout: tuple (cif_output[B,L,H], cif_length[B], fires[B,T])
    const long long fixed = (long long)B_ + (long long)B_ * T_;
    long long rem = (long long)out_size - fixed;
    int L;
    float* out_cif;
    float* out_len;
    float* out_fires;
    if (rem > 0 && rem % ((long long)B_ * H_) == 0) {
        L = (int)(rem / ((long long)B_ * H_));
        out_cif   = out;
        out_len   = out + (size_t)B_ * L * H_;
        out_fires = out_len + B_;
    } else {
        L = (int)((long long)out_size / ((long long)B_ * H_));
        out_cif = out;
        cudaGetSymbolAddress((void**)&out_len, g_dummy_len);
        cudaGetSymbolAddress((void**)&out_fires, g_dummy_fires);
    }

    alphas_kernel<<<dim3(T_ / BT, B_), 256>>>(hidden, conv_w, conv_b,
                                              lin_w, lin_b);
    scan_kernel<<<B_, 64>>>(out_fires, out_len);
    if (L > 0)
        gather_kernel<<<dim3(L, B_), 256>>>(hidden, out_cif, L);
}